// round 14
// baseline (speedup 1.0000x reference)
#include <cuda_runtime.h>
#include <math.h>

#define DD 160
#define SL 740        // hess slice: 20 rows * 37 stride
#define CSL (36*40)   // conv slice: 36 rows * 40 stride

// Scratch for conv output y [B=2, 160,160,160]
static __device__ float g_y[2 * DD * DD * DD];

static __device__ __forceinline__ int clampi(int v) {
    return min(DD - 1, max(0, v));
}

// ---------------------------------------------------------------------------
// Conv role: z-marching 3D conv 5x5x5, replicate padding, scalar FFMA.
// 128 threads. Tile 32x x 32y, 5 z. Packed load table (smem|gmem<<16).
// ---------------------------------------------------------------------------
__device__ __forceinline__ void conv_role(
    const float* __restrict__ x, const float* __restrict__ w,
    float* s, float* wsp, int bx0, int by0, int b, int z0, int tid)
{
    const int tx = tid & 3;
    const int ty = tid >> 2;

    const float* xb = x + (size_t)b * DD * DD * DD;
    float* yb = g_y + (size_t)b * DD * DD * DD;

    if (tid < 125) wsp[(tid / 5) * 8 + tid % 5] = w[tid];

    int tab[11];
#pragma unroll
    for (int k = 0; k < 11; k++) {
        int idx = tid + k * 128;
        if (idx < 1296) {
            int sy = idx / 36, sx = idx - sy * 36;
            tab[k] = (sy * 40 + sx)
                   | ((clampi(by0 + sy - 2) * DD + clampi(bx0 + sx - 2)) << 16);
        } else tab[k] = 0;
    }
    const bool hasK10 = (tid < 16);

    float acc[5][8];
#pragma unroll
    for (int g = 0; g < 5; g++)
#pragma unroll
        for (int o = 0; o < 8; o++) acc[g][o] = 0.f;

    const int xoff = tx * 8;
    const int rowbase = ty * 40 + xoff;

    auto load_slice = [&](int i) {
        float* snew = s + (i & 1) * CSL;
        const float* base = xb + (size_t)clampi(z0 - 2 + i) * (DD * DD);
#pragma unroll
        for (int k = 0; k < 10; k++) {
            int t = tab[k];
            snew[t & 0xFFFF] = __ldg(base + (t >> 16));
        }
        if (hasK10) {
            int t = tab[10];
            snew[t & 0xFFFF] = __ldg(base + (t >> 16));
        }
    };

    auto fma_gens = [&](int i, int gmin, int gmax) {
#pragma unroll
        for (int dy = 0; dy < 5; dy++) {
            const float* row = s + (i & 1) * CSL + rowbase + dy * 40;
            float4 ra = *(const float4*)(row);
            float4 rb = *(const float4*)(row + 4);
            float4 rc = *(const float4*)(row + 8);
            float r[12] = {ra.x, ra.y, ra.z, ra.w, rb.x, rb.y, rb.z, rb.w,
                           rc.x, rc.y, rc.z, rc.w};
#pragma unroll
            for (int g = 0; g < 5; g++) {
                if (g >= gmin && g < gmax) {
                    const float* wr = wsp + ((4 - g) * 5 + dy) * 8;
                    float4 wv = *(const float4*)wr;
                    float w4 = wr[4];
#pragma unroll
                    for (int o = 0; o < 8; o++) {
                        float a = acc[g][o];
                        a = fmaf(wv.x, r[o + 0], a);
                        a = fmaf(wv.y, r[o + 1], a);
                        a = fmaf(wv.z, r[o + 2], a);
                        a = fmaf(wv.w, r[o + 3], a);
                        a = fmaf(w4,   r[o + 4], a);
                        acc[g][o] = a;
                    }
                }
            }
        }
    };

    auto shift = [&]() {
#pragma unroll
        for (int g = 0; g < 4; g++)
#pragma unroll
            for (int o = 0; o < 8; o++) acc[g][o] = acc[g + 1][o];
#pragma unroll
        for (int o = 0; o < 8; o++) acc[4][o] = 0.f;
    };

    auto store_out = [&](int z) {
        float* orow = yb + (((size_t)z * DD) + (by0 + ty)) * DD + bx0 + xoff;
        float4 v0 = {acc[0][0], acc[0][1], acc[0][2], acc[0][3]};
        float4 v1 = {acc[0][4], acc[0][5], acc[0][6], acc[0][7]};
        ((float4*)orow)[0] = v0;
        ((float4*)orow)[1] = v1;
    };

#pragma unroll
    for (int i = 0; i < 4; i++) {
        load_slice(i);
        __syncthreads();
        fma_gens(i, 4 - i, 5);
        shift();
    }
    {
        load_slice(4);
        __syncthreads();
        fma_gens(4, 0, 5);
        store_out(z0);
        shift();
    }
#pragma unroll
    for (int i = 5; i < 9; i++) {
        load_slice(i);
        __syncthreads();
        fma_gens(i, 0, 9 - i);
        store_out(z0 - 4 + i);
        shift();
    }
}

// ---------------------------------------------------------------------------
// Hess role: z-marching Hessian + MLP. Packed load table.
// ---------------------------------------------------------------------------
__device__ __forceinline__ void hess_role(
    const float* __restrict__ w1, const float* __restrict__ b1,
    const float* __restrict__ w2, const float* __restrict__ b2,
    float* __restrict__ out,
    float* s, float* sw1p, float2* sb12, float* sb2s,
    int bx0, int by0, int b, int z0, int tid)
{
    const int tx  = tid & 31;
    const int tyq = tid >> 5;

    const float* yb = g_y + (size_t)b * DD * DD * DD;

    if (tid < 60)       sw1p[(tid / 6) * 8 + tid % 6] = 0.25f * w1[tid];
    else if (tid < 80)  sw1p[(tid - 60) / 2 * 8 + 6 + ((tid - 60) & 1)] = 0.f;
    else if (tid < 90)  { int o = tid - 80; float2 v; v.x = b1[o]; v.y = w2[o]; sb12[o] = v; }
    else if (tid == 90) sb2s[0] = b2[0];

    int tab[6];
#pragma unroll
    for (int k = 0; k < 6; k++) {
        int idx = tid + k * 128;
        if (idx < 720) {
            int sy = idx / 36, sx = idx - sy * 36;
            tab[k] = (sy * 37 + sx)
                   | ((clampi(by0 + sy - 2) * DD + clampi(bx0 + sx - 2)) << 16);
        } else tab[k] = 0;
    }
    const bool hasK5 = (tid < 80);

    const bool bxL = (bx0 == 0), bxR = (bx0 + 32 == DD);
    const bool byL = (by0 == 0), byR = (by0 + 16 == DD);
    const bool edge = bxL | bxR | byL | byR;

    auto load_slice = [&](int gz, float* dst) {
        if ((unsigned)gz < DD) {
            const float* base = yb + (size_t)gz * (DD * DD);
#pragma unroll
            for (int k = 0; k < 5; k++) {
                int t = tab[k];
                dst[t & 0xFFFF] = __ldg(base + (t >> 16));
            }
            if (hasK5) {
                int t = tab[5];
                dst[t & 0xFFFF] = __ldg(base + (t >> 16));
            }
        } else {
            int e; const float *p0, *p1;
            if (gz < 0) { e = -gz; p0 = yb; p1 = yb + DD * DD; }
            else        { e = gz - (DD - 1);
                          p0 = yb + (size_t)(DD - 1) * DD * DD;
                          p1 = yb + (size_t)(DD - 2) * DD * DD; }
            float w0 = 1.f + (float)e, w1n = -(float)e;
#pragma unroll
            for (int k = 0; k < 5; k++) {
                int t = tab[k]; int gm = t >> 16;
                dst[t & 0xFFFF] = w0 * __ldg(p0 + gm) + w1n * __ldg(p1 + gm);
            }
            if (hasK5) {
                int t = tab[5]; int gm = t >> 16;
                dst[t & 0xFFFF] = w0 * __ldg(p0 + gm) + w1n * __ldg(p1 + gm);
            }
        }
    };

    auto fixup = [&](float* sl) {     // warp 0 only
        if (bxL | bxR) {
            if (tx < 20) {
                float* row = sl + tx * 37;
                if (bxL) { float a = row[2],  c2 = row[3];
                           row[1]  = 2.f * a - c2; row[0]  = 3.f * a - 2.f * c2; }
                if (bxR) { float a = row[33], c2 = row[32];
                           row[34] = 2.f * a - c2; row[35] = 3.f * a - 2.f * c2; }
            }
            __syncwarp();
        }
        if (byL | byR) {
            for (int xx = tx; xx < 36; xx += 32) {
                float* p = sl + xx;
                if (byL) { float a = p[2 * 37],  c2 = p[3 * 37];
                           p[37]      = 2.f * a - c2; p[0]       = 3.f * a - 2.f * c2; }
                if (byR) { float a = p[17 * 37], c2 = p[16 * 37];
                           p[18 * 37] = 2.f * a - c2; p[19 * 37] = 3.f * a - 2.f * c2; }
            }
        }
    };

    for (int gz = z0 - 2; gz <= z0 + 1; gz++)
        load_slice(gz, s + ((gz + 16) & 7) * SL);
    __syncthreads();
    if (edge) {
        if (tid < 32)
            for (int gz = z0 - 2; gz <= z0 + 1; gz++)
                fixup(s + ((gz + 16) & 7) * SL);
        __syncthreads();
    }

    const int gx = bx0 + tx;
    const float fxc = (gx == 0 || gx == DD - 1) ? 2.f : 1.f;
    const int y4 = tyq * 4;
    const int coff = (y4 + 2) * 37 + tx + 2;
    float fyv[4];
#pragma unroll
    for (int v = 0; v < 4; v++) {
        int gy = by0 + y4 + v;
        fyv[v] = (gy == 0 || gy == DD - 1) ? 2.f : 1.f;
    }

    for (int z = z0; z < z0 + 5; z++) {
        load_slice(z + 2, s + ((z + 18) & 7) * SL);
        __syncthreads();
        if (edge) {
            if (tid < 32) fixup(s + ((z + 18) & 7) * SL);
            __syncthreads();
        }

        const float* sm2 = s + ((z + 14) & 7) * SL;
        const float* sm1 = s + ((z + 15) & 7) * SL;
        const float* sc  = s + ((z + 16) & 7) * SL;
        const float* sp1 = s + ((z + 17) & 7) * SL;
        const float* sp2 = s + ((z + 18) & 7) * SL;
        const float fz = (z == 0 || z == DD - 1) ? 2.f : 1.f;

        float h[4][6];

        float scx[8];
#pragma unroll
        for (int r = 0; r < 8; r++) scx[r] = sc[coff + (r - 2) * 37];

#pragma unroll
        for (int v = 0; v < 4; v++) {
            const int c = coff + v * 37;
            float cc = scx[v + 2];
            h[v][3] = fyv[v] * (scx[v + 4] - 2.f * cc + scx[v]);
            h[v][5] = fxc * (sc[c + 2] - 2.f * cc + sc[c - 2]);
            h[v][0] = fz * (sp2[c] - 2.f * cc + sm2[c]);
            h[v][2] = sp1[c + 1] - sp1[c - 1] - sm1[c + 1] + sm1[c - 1];
        }

        {
            float scp[6], scm[6];
#pragma unroll
            for (int r = 0; r < 6; r++) {
                scp[r] = sc[coff + (r - 1) * 37 + 1];
                scm[r] = sc[coff + (r - 1) * 37 - 1];
            }
#pragma unroll
            for (int v = 0; v < 4; v++)
                h[v][4] = scp[v + 2] - scm[v + 2] - scp[v] + scm[v];
        }

        {
            float zyd[6];
#pragma unroll
            for (int r = 0; r < 6; r++) {
                int c = coff + (r - 1) * 37;
                zyd[r] = sp1[c] - sm1[c];
            }
#pragma unroll
            for (int v = 0; v < 4; v++)
                h[v][1] = zyd[v + 2] - zyd[v];
        }

        float a2[4];
#pragma unroll
        for (int v = 0; v < 4; v++) a2[v] = sb2s[0];

#pragma unroll
        for (int o = 0; o < 10; o++) {
            float4 wa = *(const float4*)(sw1p + o * 8);
            float2 wb = *(const float2*)(sw1p + o * 8 + 4);
            float2 bw = sb12[o];
#pragma unroll
            for (int v = 0; v < 4; v++) {
                float t = bw.x;
                t = fmaf(wa.x, h[v][0], t);
                t = fmaf(wa.y, h[v][1], t);
                t = fmaf(wa.z, h[v][2], t);
                t = fmaf(wa.w, h[v][3], t);
                t = fmaf(wb.x, h[v][4], t);
                t = fmaf(wb.y, h[v][5], t);
                a2[v] = fmaf(bw.y, fmaxf(t, 0.f), a2[v]);
            }
        }

#pragma unroll
        for (int v = 0; v < 4; v++) {
            float sg = 1.f / (1.f + __expf(-a2[v]));
            out[(((size_t)b * DD + z) * DD + (by0 + y4 + v)) * DD + gx] = sg;
        }
    }
}

// ---------------------------------------------------------------------------
// Fused role-split kernel, roles INTERLEAVED across bid space so contiguous
// CTA->SM placement mixes conv and hess blocks on every SM.
//   c_before = bid*convN/totalN; conv iff (bid+1)*convN/totalN > c_before.
// ---------------------------------------------------------------------------
__global__ __launch_bounds__(128, 6) void fused_kernel(
    const float* __restrict__ x, const float* __restrict__ w,
    const float* __restrict__ w1, const float* __restrict__ b1,
    const float* __restrict__ w2, const float* __restrict__ b2,
    float* __restrict__ out,
    int convN, int totalN, int convBatch, int convChunk0,
    int hessBatch, int hessChunk0)
{
    __shared__ float sbuf[8 * SL];
    __shared__ float sw1p[80];
    __shared__ float2 sb12[10];
    __shared__ float sb2s[1];

    const int tid = threadIdx.x;
    const int bid = blockIdx.x;

    const int c_before = (int)(((long long)bid * convN) / totalN);
    const int c_after  = (int)(((long long)(bid + 1) * convN) / totalN);

    if (c_after > c_before) {
        int cb = c_before;
        int bx0 = (cb % 5) * 32;
        int by0 = ((cb / 5) % 5) * 32;
        int z0  = (convChunk0 + cb / 25) * 5;
        conv_role(x, w, sbuf, sbuf + 2 * CSL, bx0, by0, convBatch, z0, tid);
    } else {
        int hb = bid - c_before;
        int bx0 = (hb % 5) * 32;
        int by0 = ((hb / 5) % 10) * 16;
        int z0  = (hessChunk0 + hb / 50) * 5;
        hess_role(w1, b1, w2, b2, out, sbuf, sw1p, sb12, sb2s,
                  bx0, by0, hessBatch, z0, tid);
    }
}

// ---------------------------------------------------------------------------
// 5 same-stream launches (deps: hess chunk c needs conv z <= 5c+6):
//   K1: conv b0 [0,16)
//   K2: conv b0 [16,32) + hess b0 [0,15)
//   K3: conv b1 [0,16)  + hess b0 [15,32)
//   K4: conv b1 [16,32) + hess b1 [0,15)
//   K5:                   hess b1 [15,32)
// ---------------------------------------------------------------------------
extern "C" void kernel_launch(void* const* d_in, const int* in_sizes, int n_in,
                              void* d_out, int out_size)
{
    const float* x  = (const float*)d_in[0];
    const float* cw = (const float*)d_in[1];
    const float* w1 = (const float*)d_in[2];
    const float* b1 = (const float*)d_in[3];
    const float* w2 = (const float*)d_in[4];
    const float* b2 = (const float*)d_in[5];
    float* out = (float*)d_out;

    const int CONV_HALF = 5 * 5 * 16;   // 400 blocks
    const int HESS_A    = 5 * 10 * 15;  // 750 blocks
    const int HESS_B    = 5 * 10 * 17;  // 850 blocks

    fused_kernel<<<CONV_HALF, 128>>>(x, cw, w1, b1, w2, b2, out,
        CONV_HALF, CONV_HALF, 0, 0,   0, 0);
    fused_kernel<<<CONV_HALF + HESS_A, 128>>>(x, cw, w1, b1, w2, b2, out,
        CONV_HALF, CONV_HALF + HESS_A, 0, 16,  0, 0);
    fused_kernel<<<CONV_HALF + HESS_B, 128>>>(x, cw, w1, b1, w2, b2, out,
        CONV_HALF, CONV_HALF + HESS_B, 1, 0,   0, 15);
    fused_kernel<<<CONV_HALF + HESS_A, 128>>>(x, cw, w1, b1, w2, b2, out,
        CONV_HALF, CONV_HALF + HESS_A, 1, 16,  1, 0);
    fused_kernel<<<HESS_B, 128>>>(x, cw, w1, b1, w2, b2, out,
        0,         HESS_B,             0, 0,   1, 15);
}

// round 15
// speedup vs baseline: 1.4086x; 1.4086x over previous
#include <cuda_runtime.h>
#include <math.h>

#define DD 160
#define SL 740        // hess slice: 20 rows * 37 stride
#define CSL (36*40)   // conv slice: 36 rows * 40 stride

// Scratch for conv output y [B=2, 160,160,160]
static __device__ float g_y[2 * DD * DD * DD];

static __device__ __forceinline__ int clampi(int v) {
    return min(DD - 1, max(0, v));
}

// ---------------------------------------------------------------------------
// Pass 1: z-marching 3D conv 5x5x5, replicate padding, scalar FFMA.
// Chunk 5 z (+4 warmup). R11 verbatim — at scalar-FFMA floor (~53.6us).
// ---------------------------------------------------------------------------
__global__ __launch_bounds__(128) void conv3d_kernel(
    const float* __restrict__ x, const float* __restrict__ w)
{
    __shared__ float s[2 * CSL];
    __shared__ float wsp[25 * 8];

    const int tx  = threadIdx.x;
    const int ty  = threadIdx.y;
    const int tid = ty * 4 + tx;

    const int bx0 = blockIdx.x * 32;
    const int by0 = blockIdx.y * 32;
    const int b   = blockIdx.z >> 5;
    const int z0  = (blockIdx.z & 31) * 5;

    const float* xb = x + (size_t)b * DD * DD * DD;
    float* yb = g_y + (size_t)b * DD * DD * DD;

    if (tid < 125) wsp[(tid / 5) * 8 + tid % 5] = w[tid];

    int lsm[11], lgm[11];
#pragma unroll
    for (int k = 0; k < 11; k++) {
        int idx = tid + k * 128;
        if (idx < 1296) {
            int sy = idx / 36, sx = idx - sy * 36;
            lsm[k] = sy * 40 + sx;
            lgm[k] = clampi(by0 + sy - 2) * DD + clampi(bx0 + sx - 2);
        } else { lsm[k] = 0; lgm[k] = 0; }
    }
    const bool hasK10 = (tid < 16);

    float acc[5][8];
#pragma unroll
    for (int g = 0; g < 5; g++)
#pragma unroll
        for (int o = 0; o < 8; o++) acc[g][o] = 0.f;

    const int xoff = tx * 8;
    const int rowbase = ty * 40 + xoff;

    auto load_slice = [&](int i) {
        float* snew = s + (i & 1) * CSL;
        const float* base = xb + (size_t)clampi(z0 - 2 + i) * (DD * DD);
#pragma unroll
        for (int k = 0; k < 10; k++)
            snew[lsm[k]] = __ldg(base + lgm[k]);
        if (hasK10) snew[lsm[10]] = __ldg(base + lgm[10]);
    };

    auto fma_gens = [&](int i, int gmin, int gmax) {
#pragma unroll
        for (int dy = 0; dy < 5; dy++) {
            const float* row = s + (i & 1) * CSL + rowbase + dy * 40;
            float4 ra = *(const float4*)(row);
            float4 rb = *(const float4*)(row + 4);
            float4 rc = *(const float4*)(row + 8);
            float r[12] = {ra.x, ra.y, ra.z, ra.w, rb.x, rb.y, rb.z, rb.w,
                           rc.x, rc.y, rc.z, rc.w};
#pragma unroll
            for (int g = 0; g < 5; g++) {
                if (g >= gmin && g < gmax) {
                    const float* wr = wsp + ((4 - g) * 5 + dy) * 8;
                    float4 wv = *(const float4*)wr;
                    float w4 = wr[4];
#pragma unroll
                    for (int o = 0; o < 8; o++) {
                        float a = acc[g][o];
                        a = fmaf(wv.x, r[o + 0], a);
                        a = fmaf(wv.y, r[o + 1], a);
                        a = fmaf(wv.z, r[o + 2], a);
                        a = fmaf(wv.w, r[o + 3], a);
                        a = fmaf(w4,   r[o + 4], a);
                        acc[g][o] = a;
                    }
                }
            }
        }
    };

    auto shift = [&]() {
#pragma unroll
        for (int g = 0; g < 4; g++)
#pragma unroll
            for (int o = 0; o < 8; o++) acc[g][o] = acc[g + 1][o];
#pragma unroll
        for (int o = 0; o < 8; o++) acc[4][o] = 0.f;
    };

    auto store_out = [&](int z) {
        float* orow = yb + (((size_t)z * DD) + (by0 + ty)) * DD + bx0 + xoff;
        float4 v0 = {acc[0][0], acc[0][1], acc[0][2], acc[0][3]};
        float4 v1 = {acc[0][4], acc[0][5], acc[0][6], acc[0][7]};
        ((float4*)orow)[0] = v0;
        ((float4*)orow)[1] = v1;
    };

#pragma unroll
    for (int i = 0; i < 4; i++) {
        load_slice(i);
        __syncthreads();
        fma_gens(i, 4 - i, 5);
        shift();
    }
    {
        load_slice(4);
        __syncthreads();
        fma_gens(4, 0, 5);
        store_out(z0);
        shift();
    }
#pragma unroll
    for (int i = 5; i < 9; i++) {
        load_slice(i);
        __syncthreads();
        fma_gens(i, 0, 9 - i);
        store_out(z0 - 4 + i);
        shift();
    }
}

// ---------------------------------------------------------------------------
// Pass 2: z-marching Hessian + MLP (R11 body), register-trimmed for a
// NATURAL 8 blocks/SM: packed load table (smem|gmem<<16) and per-voxel
// inlined fy. Chunk 5 z, 8-slot ring.
// ---------------------------------------------------------------------------
__global__ __launch_bounds__(128, 8) void hess_mlp_kernel(
    const float* __restrict__ w1, const float* __restrict__ b1,
    const float* __restrict__ w2, const float* __restrict__ b2,
    float* __restrict__ out)
{
    __shared__ float s[8 * SL];
    __shared__ float sw1p[10 * 8];    // [o][0..5] = 0.25*w1[o][f]
    __shared__ float2 sb12[10];       // {b1[o], w2[o]}
    __shared__ float sb2s[1];

    const int tx  = threadIdx.x;   // 0..31
    const int tyq = threadIdx.y;   // 0..3
    const int tid = tyq * 32 + tx;

    const int bx0 = blockIdx.x * 32;
    const int by0 = blockIdx.y * 16;
    const int b   = blockIdx.z >> 5;
    const int z0  = (blockIdx.z & 31) * 5;

    const float* yb = g_y + (size_t)b * DD * DD * DD;

    if (tid < 60)       sw1p[(tid / 6) * 8 + tid % 6] = 0.25f * w1[tid];
    else if (tid < 80)  sw1p[(tid - 60) / 2 * 8 + 6 + ((tid - 60) & 1)] = 0.f;
    else if (tid < 90)  { int o = tid - 80; float2 v; v.x = b1[o]; v.y = w2[o]; sb12[o] = v; }
    else if (tid == 90) sb2s[0] = b2[0];

    // Packed load table: lo16 = smem offset (<=738), hi16 = gmem offset (<=25599)
    int tab[6];
#pragma unroll
    for (int k = 0; k < 6; k++) {
        int idx = tid + k * 128;
        if (idx < 720) {
            int sy = idx / 36, sx = idx - sy * 36;
            tab[k] = (sy * 37 + sx)
                   | ((clampi(by0 + sy - 2) * DD + clampi(bx0 + sx - 2)) << 16);
        } else tab[k] = 0;
    }
    const bool hasK5 = (tid < 80);

    const bool bxL = (bx0 == 0), bxR = (bx0 + 32 == DD);
    const bool byL = (by0 == 0), byR = (by0 + 16 == DD);
    const bool edge = bxL | bxR | byL | byR;

    auto load_slice = [&](int gz, float* dst) {
        if ((unsigned)gz < DD) {
            const float* base = yb + (size_t)gz * (DD * DD);
#pragma unroll
            for (int k = 0; k < 5; k++) {
                int t = tab[k];
                dst[t & 0xFFFF] = __ldg(base + (t >> 16));
            }
            if (hasK5) {
                int t = tab[5];
                dst[t & 0xFFFF] = __ldg(base + (t >> 16));
            }
        } else {
            int e; const float *p0, *p1;
            if (gz < 0) { e = -gz; p0 = yb; p1 = yb + DD * DD; }
            else        { e = gz - (DD - 1);
                          p0 = yb + (size_t)(DD - 1) * DD * DD;
                          p1 = yb + (size_t)(DD - 2) * DD * DD; }
            float w0 = 1.f + (float)e, w1n = -(float)e;
#pragma unroll
            for (int k = 0; k < 5; k++) {
                int t = tab[k]; int gm = t >> 16;
                dst[t & 0xFFFF] = w0 * __ldg(p0 + gm) + w1n * __ldg(p1 + gm);
            }
            if (hasK5) {
                int t = tab[5]; int gm = t >> 16;
                dst[t & 0xFFFF] = w0 * __ldg(p0 + gm) + w1n * __ldg(p1 + gm);
            }
        }
    };

    auto fixup = [&](float* sl) {     // warp 0 only
        if (bxL | bxR) {
            if (tx < 20) {
                float* row = sl + tx * 37;
                if (bxL) { float a = row[2],  c2 = row[3];
                           row[1]  = 2.f * a - c2; row[0]  = 3.f * a - 2.f * c2; }
                if (bxR) { float a = row[33], c2 = row[32];
                           row[34] = 2.f * a - c2; row[35] = 3.f * a - 2.f * c2; }
            }
            __syncwarp();
        }
        if (byL | byR) {
            for (int xx = tx; xx < 36; xx += 32) {
                float* p = sl + xx;
                if (byL) { float a = p[2 * 37],  c2 = p[3 * 37];
                           p[37]      = 2.f * a - c2; p[0]       = 3.f * a - 2.f * c2; }
                if (byR) { float a = p[17 * 37], c2 = p[16 * 37];
                           p[18 * 37] = 2.f * a - c2; p[19 * 37] = 3.f * a - 2.f * c2; }
            }
        }
    };

    for (int gz = z0 - 2; gz <= z0 + 1; gz++)
        load_slice(gz, s + ((gz + 16) & 7) * SL);
    __syncthreads();
    if (edge) {
        if (tid < 32)
            for (int gz = z0 - 2; gz <= z0 + 1; gz++)
                fixup(s + ((gz + 16) & 7) * SL);
        __syncthreads();
    }

    const int gx = bx0 + tx;
    const float fxc = (gx == 0 || gx == DD - 1) ? 2.f : 1.f;
    const int y4 = tyq * 4;
    const int coff = (y4 + 2) * 37 + tx + 2;

    for (int z = z0; z < z0 + 5; z++) {
        load_slice(z + 2, s + ((z + 18) & 7) * SL);
        __syncthreads();
        if (edge) {
            if (tid < 32) fixup(s + ((z + 18) & 7) * SL);
            __syncthreads();
        }

        const float* sm2 = s + ((z + 14) & 7) * SL;
        const float* sm1 = s + ((z + 15) & 7) * SL;
        const float* sc  = s + ((z + 16) & 7) * SL;
        const float* sp1 = s + ((z + 17) & 7) * SL;
        const float* sp2 = s + ((z + 18) & 7) * SL;
        const float fz = (z == 0 || z == DD - 1) ? 2.f : 1.f;

        // h values are RAW (no 0.25) — w1 is pre-scaled by 0.25.
        float h[4][6];

        float scx[8];
#pragma unroll
        for (int r = 0; r < 8; r++) scx[r] = sc[coff + (r - 2) * 37];

#pragma unroll
        for (int v = 0; v < 4; v++) {
            const int c = coff + v * 37;
            const int gy = by0 + y4 + v;
            const float fy = (gy == 0 || gy == DD - 1) ? 2.f : 1.f;
            float cc = scx[v + 2];
            h[v][3] = fy * (scx[v + 4] - 2.f * cc + scx[v]);
            h[v][5] = fxc * (sc[c + 2] - 2.f * cc + sc[c - 2]);
            h[v][0] = fz * (sp2[c] - 2.f * cc + sm2[c]);
            h[v][2] = sp1[c + 1] - sp1[c - 1] - sm1[c + 1] + sm1[c - 1];
        }

        {
            float scp[6], scm[6];
#pragma unroll
            for (int r = 0; r < 6; r++) {
                scp[r] = sc[coff + (r - 1) * 37 + 1];
                scm[r] = sc[coff + (r - 1) * 37 - 1];
            }
#pragma unroll
            for (int v = 0; v < 4; v++)
                h[v][4] = scp[v + 2] - scm[v + 2] - scp[v] + scm[v];
        }

        {
            float zyd[6];
#pragma unroll
            for (int r = 0; r < 6; r++) {
                int c = coff + (r - 1) * 37;
                zyd[r] = sp1[c] - sm1[c];
            }
#pragma unroll
            for (int v = 0; v < 4; v++)
                h[v][1] = zyd[v + 2] - zyd[v];
        }

        float a2[4];
#pragma unroll
        for (int v = 0; v < 4; v++) a2[v] = sb2s[0];

#pragma unroll
        for (int o = 0; o < 10; o++) {
            float4 wa = *(const float4*)(sw1p + o * 8);
            float2 wb = *(const float2*)(sw1p + o * 8 + 4);
            float2 bw = sb12[o];
#pragma unroll
            for (int v = 0; v < 4; v++) {
                float t = bw.x;
                t = fmaf(wa.x, h[v][0], t);
                t = fmaf(wa.y, h[v][1], t);
                t = fmaf(wa.z, h[v][2], t);
                t = fmaf(wa.w, h[v][3], t);
                t = fmaf(wb.x, h[v][4], t);
                t = fmaf(wb.y, h[v][5], t);
                a2[v] = fmaf(bw.y, fmaxf(t, 0.f), a2[v]);
            }
        }

#pragma unroll
        for (int v = 0; v < 4; v++) {
            float sg = 1.f / (1.f + __expf(-a2[v]));
            out[(((size_t)b * DD + z) * DD + (by0 + y4 + v)) * DD + gx] = sg;
        }
    }
}

// ---------------------------------------------------------------------------
// Launch: inputs per metadata order: x, conv_w, w1, b1, w2, b2
// ---------------------------------------------------------------------------
extern "C" void kernel_launch(void* const* d_in, const int* in_sizes, int n_in,
                              void* d_out, int out_size)
{
    const float* x  = (const float*)d_in[0];
    const float* cw = (const float*)d_in[1];
    const float* w1 = (const float*)d_in[2];
    const float* b1 = (const float*)d_in[3];
    const float* w2 = (const float*)d_in[4];
    const float* b2 = (const float*)d_in[5];
    float* out = (float*)d_out;

    // conv: z = 2 batches * 32 chunks of 5 -> grid 1600
    conv3d_kernel<<<dim3(5, 5, 64), dim3(4, 32, 1)>>>(x, cw);
    // hess: z = 2 * 32 -> grid 3200
    hess_mlp_kernel<<<dim3(5, 10, 64), dim3(32, 4, 1)>>>(w1, b1, w2, b2, out);
}

// round 16
// speedup vs baseline: 1.4443x; 1.0253x over previous
#include <cuda_runtime.h>
#include <math.h>

#define DD 160
#define SL 740        // hess slice: 20 rows * 37 stride
#define CSL (36*40)   // conv slice: 36 rows * 40 stride

// Scratch for conv output y [B=2, 160,160,160]
static __device__ float g_y[2 * DD * DD * DD];

static __device__ __forceinline__ int clampi(int v) {
    return min(DD - 1, max(0, v));
}

// ---------------------------------------------------------------------------
// Pass 1: z-marching 3D conv 5x5x5, replicate padding, scalar FFMA.
// Chunk 5 z (+4 warmup). Rolling acc[5][8]; static warmup/tail bounds
// (exact 125 FMA per output). At the scalar-FFMA pipe floor (~53.5us).
// ---------------------------------------------------------------------------
__global__ __launch_bounds__(128) void conv3d_kernel(
    const float* __restrict__ x, const float* __restrict__ w)
{
    __shared__ float s[2 * CSL];
    __shared__ float wsp[25 * 8];

    const int tx  = threadIdx.x;
    const int ty  = threadIdx.y;
    const int tid = ty * 4 + tx;

    const int bx0 = blockIdx.x * 32;
    const int by0 = blockIdx.y * 32;
    const int b   = blockIdx.z >> 5;
    const int z0  = (blockIdx.z & 31) * 5;

    const float* xb = x + (size_t)b * DD * DD * DD;
    float* yb = g_y + (size_t)b * DD * DD * DD;

    if (tid < 125) wsp[(tid / 5) * 8 + tid % 5] = w[tid];

    int lsm[11], lgm[11];
#pragma unroll
    for (int k = 0; k < 11; k++) {
        int idx = tid + k * 128;
        if (idx < 1296) {
            int sy = idx / 36, sx = idx - sy * 36;
            lsm[k] = sy * 40 + sx;
            lgm[k] = clampi(by0 + sy - 2) * DD + clampi(bx0 + sx - 2);
        } else { lsm[k] = 0; lgm[k] = 0; }
    }
    const bool hasK10 = (tid < 16);

    float acc[5][8];
#pragma unroll
    for (int g = 0; g < 5; g++)
#pragma unroll
        for (int o = 0; o < 8; o++) acc[g][o] = 0.f;

    const int xoff = tx * 8;
    const int rowbase = ty * 40 + xoff;

    auto load_slice = [&](int i) {
        float* snew = s + (i & 1) * CSL;
        const float* base = xb + (size_t)clampi(z0 - 2 + i) * (DD * DD);
#pragma unroll
        for (int k = 0; k < 10; k++)
            snew[lsm[k]] = __ldg(base + lgm[k]);
        if (hasK10) snew[lsm[10]] = __ldg(base + lgm[10]);
    };

    auto fma_gens = [&](int i, int gmin, int gmax) {
#pragma unroll
        for (int dy = 0; dy < 5; dy++) {
            const float* row = s + (i & 1) * CSL + rowbase + dy * 40;
            float4 ra = *(const float4*)(row);
            float4 rb = *(const float4*)(row + 4);
            float4 rc = *(const float4*)(row + 8);
            float r[12] = {ra.x, ra.y, ra.z, ra.w, rb.x, rb.y, rb.z, rb.w,
                           rc.x, rc.y, rc.z, rc.w};
#pragma unroll
            for (int g = 0; g < 5; g++) {
                if (g >= gmin && g < gmax) {
                    const float* wr = wsp + ((4 - g) * 5 + dy) * 8;
                    float4 wv = *(const float4*)wr;
                    float w4 = wr[4];
#pragma unroll
                    for (int o = 0; o < 8; o++) {
                        float a = acc[g][o];
                        a = fmaf(wv.x, r[o + 0], a);
                        a = fmaf(wv.y, r[o + 1], a);
                        a = fmaf(wv.z, r[o + 2], a);
                        a = fmaf(wv.w, r[o + 3], a);
                        a = fmaf(w4,   r[o + 4], a);
                        acc[g][o] = a;
                    }
                }
            }
        }
    };

    auto shift = [&]() {
#pragma unroll
        for (int g = 0; g < 4; g++)
#pragma unroll
            for (int o = 0; o < 8; o++) acc[g][o] = acc[g + 1][o];
#pragma unroll
        for (int o = 0; o < 8; o++) acc[4][o] = 0.f;
    };

    auto store_out = [&](int z) {
        float* orow = yb + (((size_t)z * DD) + (by0 + ty)) * DD + bx0 + xoff;
        float4 v0 = {acc[0][0], acc[0][1], acc[0][2], acc[0][3]};
        float4 v1 = {acc[0][4], acc[0][5], acc[0][6], acc[0][7]};
        ((float4*)orow)[0] = v0;
        ((float4*)orow)[1] = v1;
    };

    // Warmup: i=0..3 (gmin=4-i); full: i=4; tail: i=5..8 (gmax=9-i).
#pragma unroll
    for (int i = 0; i < 4; i++) {
        load_slice(i);
        __syncthreads();
        fma_gens(i, 4 - i, 5);
        shift();
    }
    {
        load_slice(4);
        __syncthreads();
        fma_gens(4, 0, 5);
        store_out(z0);
        shift();
    }
#pragma unroll
    for (int i = 5; i < 9; i++) {
        load_slice(i);
        __syncthreads();
        fma_gens(i, 0, 9 - i);
        store_out(z0 - 4 + i);
        shift();
    }
}

// ---------------------------------------------------------------------------
// Pass 2: z-marching Hessian + MLP (R11 body — the proven optimum:
// 72 regs natural, 7 blocks/SM, issue ~72%). Chunk 5 z, 8-slot ring.
// w1 pre-scaled by 0.25, stride-8 padded (LDS.128+LDS.64); (b1,w2) float2.
// ---------------------------------------------------------------------------
__global__ __launch_bounds__(128) void hess_mlp_kernel(
    const float* __restrict__ w1, const float* __restrict__ b1,
    const float* __restrict__ w2, const float* __restrict__ b2,
    float* __restrict__ out)
{
    __shared__ float s[8 * SL];
    __shared__ float sw1p[10 * 8];    // [o][0..5] = 0.25*w1[o][f]
    __shared__ float2 sb12[10];       // {b1[o], w2[o]}
    __shared__ float sb2s[1];

    const int tx  = threadIdx.x;   // 0..31
    const int tyq = threadIdx.y;   // 0..3
    const int tid = tyq * 32 + tx;

    const int bx0 = blockIdx.x * 32;
    const int by0 = blockIdx.y * 16;
    const int b   = blockIdx.z >> 5;
    const int z0  = (blockIdx.z & 31) * 5;

    const float* yb = g_y + (size_t)b * DD * DD * DD;

    if (tid < 60)       sw1p[(tid / 6) * 8 + tid % 6] = 0.25f * w1[tid];
    else if (tid < 80)  sw1p[(tid - 60) / 2 * 8 + 6 + ((tid - 60) & 1)] = 0.f;
    else if (tid < 90)  { int o = tid - 80; float2 v; v.x = b1[o]; v.y = w2[o]; sb12[o] = v; }
    else if (tid == 90) sb2s[0] = b2[0];

    int lsm[6], lgm[6];
#pragma unroll
    for (int k = 0; k < 6; k++) {
        int idx = tid + k * 128;
        if (idx < 720) {
            int sy = idx / 36, sx = idx - sy * 36;
            lsm[k] = sy * 37 + sx;
            lgm[k] = clampi(by0 + sy - 2) * DD + clampi(bx0 + sx - 2);
        } else { lsm[k] = 0; lgm[k] = 0; }
    }
    const bool hasK5 = (tid < 80);

    const bool bxL = (bx0 == 0), bxR = (bx0 + 32 == DD);
    const bool byL = (by0 == 0), byR = (by0 + 16 == DD);
    const bool edge = bxL | bxR | byL | byR;

    auto load_slice = [&](int gz, float* dst) {
        if ((unsigned)gz < DD) {
            const float* base = yb + (size_t)gz * (DD * DD);
#pragma unroll
            for (int k = 0; k < 5; k++)
                dst[lsm[k]] = __ldg(base + lgm[k]);
            if (hasK5) dst[lsm[5]] = __ldg(base + lgm[5]);
        } else {
            int e; const float *p0, *p1;
            if (gz < 0) { e = -gz; p0 = yb; p1 = yb + DD * DD; }
            else        { e = gz - (DD - 1);
                          p0 = yb + (size_t)(DD - 1) * DD * DD;
                          p1 = yb + (size_t)(DD - 2) * DD * DD; }
            float w0 = 1.f + (float)e, w1n = -(float)e;
#pragma unroll
            for (int k = 0; k < 5; k++)
                dst[lsm[k]] = w0 * __ldg(p0 + lgm[k]) + w1n * __ldg(p1 + lgm[k]);
            if (hasK5)
                dst[lsm[5]] = w0 * __ldg(p0 + lgm[5]) + w1n * __ldg(p1 + lgm[5]);
        }
    };

    auto fixup = [&](float* sl) {     // warp 0 only
        if (bxL | bxR) {
            if (tx < 20) {
                float* row = sl + tx * 37;
                if (bxL) { float a = row[2],  c2 = row[3];
                           row[1]  = 2.f * a - c2; row[0]  = 3.f * a - 2.f * c2; }
                if (bxR) { float a = row[33], c2 = row[32];
                           row[34] = 2.f * a - c2; row[35] = 3.f * a - 2.f * c2; }
            }
            __syncwarp();
        }
        if (byL | byR) {
            for (int xx = tx; xx < 36; xx += 32) {
                float* p = sl + xx;
                if (byL) { float a = p[2 * 37],  c2 = p[3 * 37];
                           p[37]      = 2.f * a - c2; p[0]       = 3.f * a - 2.f * c2; }
                if (byR) { float a = p[17 * 37], c2 = p[16 * 37];
                           p[18 * 37] = 2.f * a - c2; p[19 * 37] = 3.f * a - 2.f * c2; }
            }
        }
    };

    for (int gz = z0 - 2; gz <= z0 + 1; gz++)
        load_slice(gz, s + ((gz + 16) & 7) * SL);
    __syncthreads();
    if (edge) {
        if (tid < 32)
            for (int gz = z0 - 2; gz <= z0 + 1; gz++)
                fixup(s + ((gz + 16) & 7) * SL);
        __syncthreads();
    }

    const int gx = bx0 + tx;
    const float fxc = (gx == 0 || gx == DD - 1) ? 2.f : 1.f;
    const int y4 = tyq * 4;
    const int coff = (y4 + 2) * 37 + tx + 2;
    float fyv[4];
#pragma unroll
    for (int v = 0; v < 4; v++) {
        int gy = by0 + y4 + v;
        fyv[v] = (gy == 0 || gy == DD - 1) ? 2.f : 1.f;
    }
    const float b2r = sb2s[0];        // hoisted: no per-step smem re-read

    for (int z = z0; z < z0 + 5; z++) {
        load_slice(z + 2, s + ((z + 18) & 7) * SL);
        __syncthreads();
        if (edge) {
            if (tid < 32) fixup(s + ((z + 18) & 7) * SL);
            __syncthreads();
        }

        const float* sm2 = s + ((z + 14) & 7) * SL;
        const float* sm1 = s + ((z + 15) & 7) * SL;
        const float* sc  = s + ((z + 16) & 7) * SL;
        const float* sp1 = s + ((z + 17) & 7) * SL;
        const float* sp2 = s + ((z + 18) & 7) * SL;
        const float fz = (z == 0 || z == DD - 1) ? 2.f : 1.f;

        // h values are RAW (no 0.25) — w1 is pre-scaled by 0.25.
        float h[4][6];

        float scx[8];
#pragma unroll
        for (int r = 0; r < 8; r++) scx[r] = sc[coff + (r - 2) * 37];

#pragma unroll
        for (int v = 0; v < 4; v++) {
            const int c = coff + v * 37;
            float cc = scx[v + 2];
            h[v][3] = fyv[v] * (scx[v + 4] - 2.f * cc + scx[v]);
            h[v][5] = fxc * (sc[c + 2] - 2.f * cc + sc[c - 2]);
            h[v][0] = fz * (sp2[c] - 2.f * cc + sm2[c]);
            h[v][2] = sp1[c + 1] - sp1[c - 1] - sm1[c + 1] + sm1[c - 1];
        }

        {
            float scp[6], scm[6];
#pragma unroll
            for (int r = 0; r < 6; r++) {
                scp[r] = sc[coff + (r - 1) * 37 + 1];
                scm[r] = sc[coff + (r - 1) * 37 - 1];
            }
#pragma unroll
            for (int v = 0; v < 4; v++)
                h[v][4] = scp[v + 2] - scm[v + 2] - scp[v] + scm[v];
        }

        {
            float zyd[6];
#pragma unroll
            for (int r = 0; r < 6; r++) {
                int c = coff + (r - 1) * 37;
                zyd[r] = sp1[c] - sm1[c];
            }
#pragma unroll
            for (int v = 0; v < 4; v++)
                h[v][1] = zyd[v + 2] - zyd[v];
        }

        float a2[4];
#pragma unroll
        for (int v = 0; v < 4; v++) a2[v] = b2r;

#pragma unroll
        for (int o = 0; o < 10; o++) {
            float4 wa = *(const float4*)(sw1p + o * 8);
            float2 wb = *(const float2*)(sw1p + o * 8 + 4);
            float2 bw = sb12[o];
#pragma unroll
            for (int v = 0; v < 4; v++) {
                float t = bw.x;
                t = fmaf(wa.x, h[v][0], t);
                t = fmaf(wa.y, h[v][1], t);
                t = fmaf(wa.z, h[v][2], t);
                t = fmaf(wa.w, h[v][3], t);
                t = fmaf(wb.x, h[v][4], t);
                t = fmaf(wb.y, h[v][5], t);
                a2[v] = fmaf(bw.y, fmaxf(t, 0.f), a2[v]);
            }
        }

#pragma unroll
        for (int v = 0; v < 4; v++) {
            float sg = 1.f / (1.f + __expf(-a2[v]));
            out[(((size_t)b * DD + z) * DD + (by0 + y4 + v)) * DD + gx] = sg;
        }
    }
}

// ---------------------------------------------------------------------------
// Launch: inputs per metadata order: x, conv_w, w1, b1, w2, b2
// ---------------------------------------------------------------------------
extern "C" void kernel_launch(void* const* d_in, const int* in_sizes, int n_in,
                              void* d_out, int out_size)
{
    const float* x  = (const float*)d_in[0];
    const float* cw = (const float*)d_in[1];
    const float* w1 = (const float*)d_in[2];
    const float* b1 = (const float*)d_in[3];
    const float* w2 = (const float*)d_in[4];
    const float* b2 = (const float*)d_in[5];
    float* out = (float*)d_out;

    // conv: z = 2 batches * 32 chunks of 5 -> grid 1600
    conv3d_kernel<<<dim3(5, 5, 64), dim3(4, 32, 1)>>>(x, cw);
    // hess: z = 2 * 32 -> grid 3200
    hess_mlp_kernel<<<dim3(5, 10, 64), dim3(32, 4, 1)>>>(w1, b1, w2, b2, out);
}